// round 13
// baseline (speedup 1.0000x reference)
#include <cuda_runtime.h>
#include <cstdint>

// ---------------------------------------------------------------------------
// Scratch
// ---------------------------------------------------------------------------
__device__ int    g_fps_idx[8 * 4096];
__device__ float4 g_sorted[8 * 8192];     // per-batch spatially sorted points

typedef unsigned long long u64;

// Packed f32x2 add (per-lane IEEE rn — proven bitwise == scalar FADD in R6)
__device__ __forceinline__ u64 pack2(float a, float b) {
    u64 r; asm("mov.b64 %0, {%1, %2};" : "=l"(r) : "f"(a), "f"(b)); return r;
}
__device__ __forceinline__ void unpack2(u64 v, float& a, float& b) {
    asm("mov.b64 {%0, %1}, %2;" : "=f"(a), "=f"(b) : "l"(v));
}
__device__ __forceinline__ u64 add2(u64 a, u64 b) {
    u64 r; asm("add.rn.f32x2 %0, %1, %2;" : "=l"(r) : "l"(a), "l"(b)); return r;
}

// 8x8x8 Morton cell over [-4, 4]
__device__ __forceinline__ int cell_of(float x, float y, float z) {
    int cx = min(max((int)(x + 4.0f), 0), 7);
    int cy = min(max((int)(y + 4.0f), 0), 7);
    int cz = min(max((int)(z + 4.0f), 0), 7);
    return (cx & 1) | ((cy & 1) << 1) | ((cz & 1) << 2)
         | (((cx >> 1) & 1) << 3) | (((cy >> 1) & 1) << 4) | (((cz >> 1) & 1) << 5)
         | ((cx >> 2) << 6) | ((cy >> 2) << 7) | ((cz >> 2) << 8);
}

// Dummy kernel: three of these shift ncu's fixed capture slot (launch index
// 3) onto the level-1 FPS kernel.
__global__ void probe_align_kernel() {}

// ---------------------------------------------------------------------------
// Level-1 FPS: 512 threads (16 warps), K=16 points/thread, 4 regions/warp.
//
// Keys are u64: (dist_bits << 32) | comp13, comp13 = 8191 - orig_idx.
// u64 max == (value desc, orig index asc) == exact jnp.argmax semantics
// (formulation bit-validated in R7). Region = k in [4r, 4r+4) = 128
// consecutive Morton-sorted points -> tight bbox. Cached region keys are
// exact (every failing region is recomputed); passing regions are safe by
// the monotone a*a+b*b+c*c skip argument (R8-proven).
//
// Per iteration: publish cached warp key (STS.64) -> __syncthreads ->
// stage-2 redux over 16 keys -> winner coords (LDS.128) -> warp bbox test
// (skip) -> lane-parallel region bbox tests (ballot) -> update only failing
// regions (packed-add subtraction == scalar FADD, verbatim scalar squared
// sum) -> pipelined per-region redux -> refresh warp key.
//
// NESTED-FPS THEOREM (R12-proven): levels 2-4 FPS == identity, so this is
// the only FPS kernel.
// ---------------------------------------------------------------------------
template <int N>
__global__ __launch_bounds__(512, 1)
void fps_kernel(const float* __restrict__ pts, int C, int npoints,
                int* __restrict__ idx_out, float4* __restrict__ sorted_g)
{
    constexpr int T = 512, NW = 16, K = 16, KP = 8, R = 4;

    extern __shared__ float4 sxyz[];          // N entries, ORIGINAL order
    __shared__ u64    rkeypub[2][NW];
    __shared__ float4 rbb[NW][R][2];          // region bbox: [0]=min [1]=max
    __shared__ int    hist[512];
    __shared__ int    offs[512];

    const int b    = blockIdx.x;
    const int t    = threadIdx.x;
    const int lane = t & 31;
    const int wid  = t >> 5;

    const float* base = pts + (size_t)b * N * C;
    float4* sorted = sorted_g + (size_t)b * N;

    // ---- load orig-order copy + cell histogram ----
    hist[t] = 0;
    __syncthreads();
#pragma unroll
    for (int k = 0; k < K; ++k) {
        int i = t + k * T;
        const float* r = base + (size_t)i * C;
        float xx = r[0], yy = r[1], zz = r[2];
        sxyz[i] = make_float4(xx, yy, zz, 0.f);
        atomicAdd(&hist[cell_of(xx, yy, zz)], 1);
    }
    __syncthreads();
    if (t == 0) {
        int s = 0;
        for (int c = 0; c < 512; ++c) { offs[c] = s; s += hist[c]; }
    }
    __syncthreads();
#pragma unroll
    for (int k = 0; k < K; ++k) {
        int i = t + k * T;
        float4 q = sxyz[i];
        int pos = atomicAdd(&offs[cell_of(q.x, q.y, q.z)], 1);
        sorted[pos] = make_float4(q.x, q.y, q.z, __int_as_float(i));
    }
    __syncthreads();

    // ---- load my sorted points; packed comp13 (2 x 16-bit per reg) ----
    float xr[K], yr[K], zr[K], d[K];
    unsigned cpk[KP];
#pragma unroll
    for (int j = 0; j < KP; ++j) {
        int k0 = 2 * j;
        int s0 = wid * (32 * K) + k0 * 32 + lane;
        int s1 = s0 + 32;
        float4 a = sorted[s0];
        float4 c = sorted[s1];
        xr[k0] = a.x; yr[k0] = a.y; zr[k0] = a.z;
        xr[k0 + 1] = c.x; yr[k0 + 1] = c.y; zr[k0 + 1] = c.z;
        unsigned c0 = 8191u - (unsigned)__float_as_int(a.w);
        unsigned c1 = 8191u - (unsigned)__float_as_int(c.w);
        cpk[j] = c0 | (c1 << 16);
    }

    // ---- region bboxes (k in [4r,4r+4)) + warp bbox ----
    float wmnx = 1e30f, wmny = 1e30f, wmnz = 1e30f;
    float wmxx = -1e30f, wmxy = -1e30f, wmxz = -1e30f;
#pragma unroll
    for (int r = 0; r < R; ++r) {
        float mnx = 1e30f, mny = 1e30f, mnz = 1e30f;
        float mxx = -1e30f, mxy = -1e30f, mxz = -1e30f;
#pragma unroll
        for (int k = 4 * r; k < 4 * r + 4; ++k) {
            mnx = fminf(mnx, xr[k]); mxx = fmaxf(mxx, xr[k]);
            mny = fminf(mny, yr[k]); mxy = fmaxf(mxy, yr[k]);
            mnz = fminf(mnz, zr[k]); mxz = fmaxf(mxz, zr[k]);
        }
#pragma unroll
        for (int o = 16; o > 0; o >>= 1) {
            mnx = fminf(mnx, __shfl_xor_sync(0xffffffffu, mnx, o));
            mny = fminf(mny, __shfl_xor_sync(0xffffffffu, mny, o));
            mnz = fminf(mnz, __shfl_xor_sync(0xffffffffu, mnz, o));
            mxx = fmaxf(mxx, __shfl_xor_sync(0xffffffffu, mxx, o));
            mxy = fmaxf(mxy, __shfl_xor_sync(0xffffffffu, mxy, o));
            mxz = fmaxf(mxz, __shfl_xor_sync(0xffffffffu, mxz, o));
        }
        if (lane == 0) {
            rbb[wid][r][0] = make_float4(mnx, mny, mnz, 0.f);
            rbb[wid][r][1] = make_float4(mxx, mxy, mxz, 0.f);
        }
        wmnx = fminf(wmnx, mnx); wmxx = fmaxf(wmxx, mxx);
        wmny = fminf(wmny, mny); wmxy = fmaxf(wmxy, mxy);
        wmnz = fminf(wmnz, mnz); wmxz = fmaxf(wmxz, mxz);
    }
    __syncwarp();

    // ---- packed coord registers ----
    u64 xp[KP], yp[KP], zp[KP];
#pragma unroll
    for (int j = 0; j < KP; ++j) {
        xp[j] = pack2(xr[2 * j], xr[2 * j + 1]);
        yp[j] = pack2(yr[2 * j], yr[2 * j + 1]);
        zp[j] = pack2(zr[2 * j], zr[2 * j + 1]);
    }

    if (t == 0) idx_out[b * npoints] = 0;

    // ---- initial distances to point 0 (verbatim scalar) + region keys ----
    u64 rk[R];                                // warp-uniform region keys
    {
        float4 q = sxyz[0];
        float px = q.x, py = q.y, pz = q.z;
        u64 bk[R];
#pragma unroll
        for (int r = 0; r < R; ++r) bk[r] = 0;
#pragma unroll
        for (int k = 0; k < K; ++k) {
            float dx = xr[k] - px, dy = yr[k] - py, dz = zr[k] - pz;
            d[k] = dx * dx + dy * dy + dz * dz;
            unsigned cc = (cpk[k >> 1] >> ((k & 1) * 16)) & 0xFFFFu;
            u64 key = ((u64)__float_as_uint(d[k]) << 32) | (u64)cc;
            int r = k >> 2;
            if (key > bk[r]) bk[r] = key;
        }
#pragma unroll
        for (int r = 0; r < R; ++r) {
            unsigned hb = (unsigned)(bk[r] >> 32);
            unsigned m  = __reduce_max_sync(0xffffffffu, hb);
            unsigned cd = (hb == m) ? (unsigned)bk[r] : 0u;
            unsigned c  = __reduce_max_sync(0xffffffffu, cd);
            rk[r] = ((u64)m << 32) | (u64)c;
        }
    }
    u64 vkey = rk[0];                         // this lane's region key copy
#pragma unroll
    for (int r = 1; r < R; ++r) if ((lane & 3) == r) vkey = rk[r];
    u64 wkey = rk[0];
#pragma unroll
    for (int r = 1; r < R; ++r) if (rk[r] > wkey) wkey = rk[r];

    for (int it = 1; it < npoints; ++it) {
        const int p = it & 1;
        if (lane == 0) rkeypub[p][wid] = wkey;
        __syncthreads();

        // stage 2: reduce the 16 warp keys
        u64 kk = rkeypub[p][lane & (NW - 1)];
        unsigned vw = (unsigned)(kk >> 32);
        unsigned iw = (unsigned)kk;
        unsigned m2 = __reduce_max_sync(0xffffffffu, vw);
        unsigned c2 = (vw == m2) ? iw : 0u;
        unsigned comp2 = __reduce_max_sync(0xffffffffu, c2);
        int bsel = 8191 - (int)comp2;               // ORIGINAL index

        if (t == 0) idx_out[b * npoints + it] = bsel;

        float4 q = sxyz[bsel];
        float px = q.x, py = q.y, pz = q.z;

        // warp-level exact bbox skip test
        float ax = fmaxf(fmaxf(wmnx - px, px - wmxx), 0.f);
        float ay = fmaxf(fmaxf(wmny - py, py - wmxy), 0.f);
        float az = fmaxf(fmaxf(wmnz - pz, pz - wmxz), 0.f);
        float mind2w = ax * ax + ay * ay + az * az;
        if (mind2w >= __uint_as_float((unsigned)(wkey >> 32))) continue;

        // lane-parallel region tests (lane&3 -> region; bits 4..31 masked)
        unsigned mask;
        {
            int rr = lane & 3;
            float4 mn = rbb[wid][rr][0];
            float4 mx = rbb[wid][rr][1];
            float bx = fmaxf(fmaxf(mn.x - px, px - mx.x), 0.f);
            float by = fmaxf(fmaxf(mn.y - py, py - mx.y), 0.f);
            float bz = fmaxf(fmaxf(mn.z - pz, pz - mx.z), 0.f);
            float mind2r = bx * bx + by * by + bz * bz;
            bool fail = mind2r < __uint_as_float((unsigned)(vkey >> 32));
            mask = __ballot_sync(0xffffffffu, fail) & 0xFu;
        }
        if (!mask) continue;

        // update failing regions (packed-add + verbatim scalar squared-sum)
        const u64 nxp = pack2(-px, -px);
        const u64 nyp = pack2(-py, -py);
        const u64 nzp = pack2(-pz, -pz);
        u64 nbk[R];
#pragma unroll
        for (int r = 0; r < R; ++r) {
            nbk[r] = 0;
            if (mask & (1u << r)) {
#pragma unroll
                for (int j = 2 * r; j < 2 * r + 2; ++j) {
                    float dx0, dx1, dy0, dy1, dz0, dz1;
                    unpack2(add2(xp[j], nxp), dx0, dx1);
                    unpack2(add2(yp[j], nyp), dy0, dy1);
                    unpack2(add2(zp[j], nzp), dz0, dz1);
                    float nd0 = dx0 * dx0 + dy0 * dy0 + dz0 * dz0;
                    float nd1 = dx1 * dx1 + dy1 * dy1 + dz1 * dz1;
                    float dk0 = fminf(d[2 * j],     nd0);
                    float dk1 = fminf(d[2 * j + 1], nd1);
                    d[2 * j]     = dk0;
                    d[2 * j + 1] = dk1;
                    unsigned c0 = cpk[j] & 0xFFFFu;
                    unsigned c1 = cpk[j] >> 16;
                    u64 key0 = ((u64)__float_as_uint(dk0) << 32) | (u64)c0;
                    u64 key1 = ((u64)__float_as_uint(dk1) << 32) | (u64)c1;
                    if (key0 > nbk[r]) nbk[r] = key0;
                    if (key1 > nbk[r]) nbk[r] = key1;
                }
            }
        }
        // pipelined per-region redux (independent ops)
        unsigned mr[R];
#pragma unroll
        for (int r = 0; r < R; ++r)
            if (mask & (1u << r))
                mr[r] = __reduce_max_sync(0xffffffffu, (unsigned)(nbk[r] >> 32));
#pragma unroll
        for (int r = 0; r < R; ++r) {
            if (mask & (1u << r)) {
                unsigned cd = ((unsigned)(nbk[r] >> 32) == mr[r]) ? (unsigned)nbk[r] : 0u;
                unsigned cr = __reduce_max_sync(0xffffffffu, cd);
                rk[r] = ((u64)mr[r] << 32) | (u64)cr;
                if ((lane & 3) == r) vkey = rk[r];
            }
        }
        wkey = rk[0];
#pragma unroll
        for (int r = 1; r < R; ++r) if (rk[r] > wkey) wkey = rk[r];
    }
}

// ---------------------------------------------------------------------------
// Gather + pointwise 2-layer MLP + output assembly.
// IDENT=true: downsample row index == output row index (nested-FPS theorem).
// ---------------------------------------------------------------------------
template <int CPREV, int F, bool REPEAT, bool IDENT>
__global__ __launch_bounds__(256)
void mlp_kernel(const float* __restrict__ in, const int* __restrict__ idx,
                const float* __restrict__ w1, const float* __restrict__ b1,
                const float* __restrict__ w2, const float* __restrict__ b2,
                float* __restrict__ out, int n_in, int npoints)
{
    constexpr int PPB = 256 / F;
    constexpr int CIN = REPEAT ? 2 * CPREV : CPREV;

    __shared__ float row[PPB][CPREV];
    __shared__ float hsm[PPB][F];

    const int t  = threadIdx.x;
    const int lp = t / F;
    const int g  = t % F;
    const int gp = blockIdx.x * PPB + lp;
    const int b  = gp / npoints;
    const int pt = gp % npoints;

    const int src = IDENT ? pt : idx[b * npoints + pt];
    const float* r = in + ((size_t)b * n_in + src) * CPREV;
    if (g < CPREV) row[lp][g] = r[g];
    __syncthreads();

    float acc = b1[g];
#pragma unroll
    for (int c = 0; c < CIN; ++c)
        acc += row[lp][c % CPREV] * w1[c * F + g];
    hsm[lp][g] = fmaxf(acc, 0.0f);
    __syncthreads();

    float o = b2[g];
#pragma unroll
    for (int j = 0; j < F; ++j)
        o += hsm[lp][j] * w2[j * F + g];

    float* orow = out + ((size_t)b * npoints + pt) * F;
    orow[g] = (g < 3) ? row[lp][g] : o;
}

// ---------------------------------------------------------------------------
// Launch
// ---------------------------------------------------------------------------
extern "C" void kernel_launch(void* const* d_in, const int* in_sizes, int n_in_cnt,
                              void* d_out, int out_size)
{
    (void)in_sizes; (void)n_in_cnt; (void)out_size;

    const float* pts  = (const float*)d_in[0];
    const float* w1_1 = (const float*)d_in[1];
    const float* b1_1 = (const float*)d_in[2];
    const float* w2_1 = (const float*)d_in[3];
    const float* b2_1 = (const float*)d_in[4];
    const float* w1_2 = (const float*)d_in[5];
    const float* b1_2 = (const float*)d_in[6];
    const float* w2_2 = (const float*)d_in[7];
    const float* b2_2 = (const float*)d_in[8];
    const float* w1_3 = (const float*)d_in[9];
    const float* b1_3 = (const float*)d_in[10];
    const float* w2_3 = (const float*)d_in[11];
    const float* b2_3 = (const float*)d_in[12];
    const float* w1_4 = (const float*)d_in[13];
    const float* b1_4 = (const float*)d_in[14];
    const float* w2_4 = (const float*)d_in[15];
    const float* b2_4 = (const float*)d_in[16];

    float* out = (float*)d_out;
    const int B = 8;
    float* f1 = out;                        // [8,4096,16]
    float* f2 = out + 8 * 4096 * 16;        // [8,2048,32]
    float* f3 = f2 + 8 * 2048 * 32;         // [8,1024,64]
    float* f4 = f3 + 8 * 1024 * 64;         // [8, 512,128]

    static int*    idx_buf = nullptr;
    static float4* sort_buf = nullptr;
    if (!idx_buf)  cudaGetSymbolAddress((void**)&idx_buf,  g_fps_idx);
    if (!sort_buf) cudaGetSymbolAddress((void**)&sort_buf, g_sorted);

    static bool attr_done = false;
    if (!attr_done) {
        cudaFuncSetAttribute(fps_kernel<8192>,
                             cudaFuncAttributeMaxDynamicSharedMemorySize, 8192 * 16);
        attr_done = true;
    }

    // Slot shims: launch indices 0-2, so ncu's fixed capture slot (index 3)
    // lands on the level-1 FPS kernel.
    probe_align_kernel<<<1, 32>>>();
    probe_align_kernel<<<1, 32>>>();
    probe_align_kernel<<<1, 32>>>();

    // ---- Level 1: 8192 -> 4096 — the ONLY FPS run ----
    fps_kernel<8192><<<B, 512, 8192 * 16>>>(pts, 3, 4096, idx_buf, sort_buf);
    mlp_kernel<3, 16, true, false><<<(B * 4096) / 16, 256>>>(
        pts, idx_buf, w1_1, b1_1, w2_1, b2_1, f1, 8192, 4096);

    // ---- Levels 2-4: nested-FPS theorem -> identity downsample ----
    mlp_kernel<16, 32, false, true><<<(B * 2048) / 8, 256>>>(
        f1, idx_buf, w1_2, b1_2, w2_2, b2_2, f2, 4096, 2048);

    mlp_kernel<32, 64, false, true><<<(B * 1024) / 4, 256>>>(
        f2, idx_buf, w1_3, b1_3, w2_3, b2_3, f3, 2048, 1024);

    mlp_kernel<64, 128, false, true><<<(B * 512) / 2, 256>>>(
        f3, idx_buf, w1_4, b1_4, w2_4, b2_4, f4, 1024, 512);
}

// round 14
// speedup vs baseline: 1.4526x; 1.4526x over previous
#include <cuda_runtime.h>
#include <cstdint>

// ---------------------------------------------------------------------------
// Scratch
// ---------------------------------------------------------------------------
__device__ int    g_fps_idx[8 * 4096];
__device__ float4 g_sorted[8 * 8192];     // per-batch spatially sorted points

typedef unsigned long long u64;

// Packed f32x2 add (per-lane IEEE rn — proven bitwise == scalar FADD in R6)
__device__ __forceinline__ u64 pack2(float a, float b) {
    u64 r; asm("mov.b64 %0, {%1, %2};" : "=l"(r) : "f"(a), "f"(b)); return r;
}
__device__ __forceinline__ void unpack2(u64 v, float& a, float& b) {
    asm("mov.b64 {%0, %1}, %2;" : "=f"(a), "=f"(b) : "l"(v));
}
__device__ __forceinline__ u64 add2(u64 a, u64 b) {
    u64 r; asm("add.rn.f32x2 %0, %1, %2;" : "=l"(r) : "l"(a), "l"(b)); return r;
}

// 8x8x8 Morton cell over [-4, 4]
__device__ __forceinline__ int cell_of(float x, float y, float z) {
    int cx = min(max((int)(x + 4.0f), 0), 7);
    int cy = min(max((int)(y + 4.0f), 0), 7);
    int cz = min(max((int)(z + 4.0f), 0), 7);
    return (cx & 1) | ((cy & 1) << 1) | ((cz & 1) << 2)
         | (((cx >> 1) & 1) << 3) | (((cy >> 1) & 1) << 4) | (((cz >> 1) & 1) << 5)
         | ((cx >> 2) << 6) | ((cy >> 2) << 7) | ((cz >> 2) << 8);
}

// Dummy kernel: three of these shift ncu's fixed capture slot (launch index
// 3) onto the level-1 FPS kernel.
__global__ void probe_align_kernel() {}

// ---------------------------------------------------------------------------
// Level-1 FPS: 512 threads (16 warps), K=16 pts/thread, TWO in-register
// regions per warp (k in [0,8) and [8,16) = two contiguous 256-slot Morton
// ranges). Region bboxes + u64 keys live in registers (warp-uniform); the
// test path has NO smem loads and NO ballot — the R13 failure modes
// (smem bbox LDS, ballot, 4 serialized redux chains, 128-reg spills) are
// all removed. comp13 = 8191 - orig_idx, packed 2x16-bit per register.
//
// Keys: (dist_bits << 32) | comp13. u64 max == (value desc, orig idx asc)
// == exact jnp.argmax (bit-validated in R7/R12). First-occurrence ties
// inside a region: per-region insertion sort by orig idx; across regions:
// the u64 key compare. Passing regions are exact by the monotone
// a*a+b*b+c*c skip argument (R8-proven); the winner's own region always
// fails its test (mind2 = 0) so it is always updated.
//
// NESTED-FPS THEOREM (R12-proven): levels 2-4 FPS == identity.
// ---------------------------------------------------------------------------
template <int N>
__global__ __launch_bounds__(512, 1)
void fps_kernel(const float* __restrict__ pts, int C, int npoints,
                int* __restrict__ idx_out, float4* __restrict__ sorted_g)
{
    constexpr int T = 512, NW = 16, K = 16, KP = 8;

    extern __shared__ float4 sxyz[];          // N entries, ORIGINAL order
    __shared__ u64 rkeypub[2][NW];
    __shared__ int hist[512];
    __shared__ int offs[512];

    const int b    = blockIdx.x;
    const int t    = threadIdx.x;
    const int lane = t & 31;
    const int wid  = t >> 5;

    const float* base = pts + (size_t)b * N * C;
    float4* sorted = sorted_g + (size_t)b * N;

    // ---- load orig-order copy + cell histogram ----
    hist[t] = 0;
    __syncthreads();
#pragma unroll
    for (int k = 0; k < K; ++k) {
        int i = t + k * T;
        const float* r = base + (size_t)i * C;
        float xx = r[0], yy = r[1], zz = r[2];
        sxyz[i] = make_float4(xx, yy, zz, 0.f);
        atomicAdd(&hist[cell_of(xx, yy, zz)], 1);
    }
    __syncthreads();
    if (t == 0) {
        int s = 0;
        for (int c = 0; c < 512; ++c) { offs[c] = s; s += hist[c]; }
    }
    __syncthreads();
#pragma unroll
    for (int k = 0; k < K; ++k) {
        int i = t + k * T;
        float4 q = sxyz[i];
        int pos = atomicAdd(&offs[cell_of(q.x, q.y, q.z)], 1);
        sorted[pos] = make_float4(q.x, q.y, q.z, __int_as_float(i));
    }
    __syncthreads();

    // ---- load my sorted points ----
    float xr[K], yr[K], zr[K], d[K];
    unsigned cf[K];                           // comp13 = 8191 - orig_idx
#pragma unroll
    for (int k = 0; k < K; ++k) {
        int slot = wid * (32 * K) + k * 32 + lane;
        float4 s = sorted[slot];
        xr[k] = s.x; yr[k] = s.y; zr[k] = s.z;
        cf[k] = 8191u - (unsigned)__float_as_int(s.w);
    }

    // ---- per-REGION insertion sort by orig idx ascending (comp desc) ----
#pragma unroll
    for (int r = 0; r < 2; ++r) {
#pragma unroll
        for (int a = 8 * r + 1; a < 8 * r + 8; ++a) {
#pragma unroll
            for (int c = a; c > 8 * r; --c) {
                bool sw = cf[c] > cf[c - 1];
                float tf; unsigned tu;
                tf = sw ? xr[c] : xr[c - 1]; xr[c] = sw ? xr[c - 1] : xr[c]; xr[c - 1] = tf;
                tf = sw ? yr[c] : yr[c - 1]; yr[c] = sw ? yr[c - 1] : yr[c]; yr[c - 1] = tf;
                tf = sw ? zr[c] : zr[c - 1]; zr[c] = sw ? zr[c - 1] : zr[c]; zr[c - 1] = tf;
                tu = sw ? cf[c] : cf[c - 1]; cf[c] = sw ? cf[c - 1] : cf[c]; cf[c - 1] = tu;
            }
        }
    }

    // pack comp13 2x16-bit per register
    unsigned cpk[KP];
#pragma unroll
    for (int j = 0; j < KP; ++j) cpk[j] = cf[2 * j] | (cf[2 * j + 1] << 16);

    // ---- two register-resident region bboxes ----
    float b0nx, b0ny, b0nz, b0xx, b0xy, b0xz;
    float b1nx, b1ny, b1nz, b1xx, b1xy, b1xz;
#pragma unroll
    for (int r = 0; r < 2; ++r) {
        float mnx = 1e30f, mny = 1e30f, mnz = 1e30f;
        float mxx = -1e30f, mxy = -1e30f, mxz = -1e30f;
#pragma unroll
        for (int k = 8 * r; k < 8 * r + 8; ++k) {
            mnx = fminf(mnx, xr[k]); mxx = fmaxf(mxx, xr[k]);
            mny = fminf(mny, yr[k]); mxy = fmaxf(mxy, yr[k]);
            mnz = fminf(mnz, zr[k]); mxz = fmaxf(mxz, zr[k]);
        }
#pragma unroll
        for (int o = 16; o > 0; o >>= 1) {
            mnx = fminf(mnx, __shfl_xor_sync(0xffffffffu, mnx, o));
            mny = fminf(mny, __shfl_xor_sync(0xffffffffu, mny, o));
            mnz = fminf(mnz, __shfl_xor_sync(0xffffffffu, mnz, o));
            mxx = fmaxf(mxx, __shfl_xor_sync(0xffffffffu, mxx, o));
            mxy = fmaxf(mxy, __shfl_xor_sync(0xffffffffu, mxy, o));
            mxz = fmaxf(mxz, __shfl_xor_sync(0xffffffffu, mxz, o));
        }
        if (r == 0) { b0nx = mnx; b0ny = mny; b0nz = mnz; b0xx = mxx; b0xy = mxy; b0xz = mxz; }
        else        { b1nx = mnx; b1ny = mny; b1nz = mnz; b1xx = mxx; b1xy = mxy; b1xz = mxz; }
    }

    // ---- packed coord registers ----
    u64 xp[KP], yp[KP], zp[KP];
#pragma unroll
    for (int j = 0; j < KP; ++j) {
        xp[j] = pack2(xr[2 * j], xr[2 * j + 1]);
        yp[j] = pack2(yr[2 * j], yr[2 * j + 1]);
        zp[j] = pack2(zr[2 * j], zr[2 * j + 1]);
    }

    if (t == 0) idx_out[b * npoints] = 0;

    // ---- initial distances to point 0 (verbatim scalar) + region keys ----
    u64 rk0, rk1;
    {
        float4 q = sxyz[0];
        float px = q.x, py = q.y, pz = q.z;
#pragma unroll
        for (int r = 0; r < 2; ++r) {
            float bv = -1.0f; unsigned bc = 0;
#pragma unroll
            for (int k = 8 * r; k < 8 * r + 8; ++k) {
                float dx = xr[k] - px, dy = yr[k] - py, dz = zr[k] - pz;
                d[k] = dx * dx + dy * dy + dz * dz;
                if (d[k] > bv) { bv = d[k]; bc = cf[k]; }
            }
            unsigned ub = __float_as_uint(bv);
            unsigned m  = __reduce_max_sync(0xffffffffu, ub);
            unsigned cd = (ub == m) ? bc : 0u;
            unsigned cc = __reduce_max_sync(0xffffffffu, cd);
            if (r == 0) rk0 = ((u64)m << 32) | (u64)cc;
            else        rk1 = ((u64)m << 32) | (u64)cc;
        }
    }
    u64 wkey = rk0 > rk1 ? rk0 : rk1;

    for (int it = 1; it < npoints; ++it) {
        const int p = it & 1;
        if (lane == 0) rkeypub[p][wid] = wkey;
        __syncthreads();

        // stage 2: reduce the 16 warp keys
        u64 kk = rkeypub[p][lane & (NW - 1)];
        unsigned vw = (unsigned)(kk >> 32);
        unsigned iw = (unsigned)kk;
        unsigned m2 = __reduce_max_sync(0xffffffffu, vw);
        unsigned c2 = (vw == m2) ? iw : 0u;
        unsigned comp2 = __reduce_max_sync(0xffffffffu, c2);
        int bsel = 8191 - (int)comp2;               // ORIGINAL index

        if (t == 0) idx_out[b * npoints + it] = bsel;

        float4 q = sxyz[bsel];
        float px = q.x, py = q.y, pz = q.z;

        // warp-uniform register region tests (exact, monotone-safe)
        float a0 = fmaxf(fmaxf(b0nx - px, px - b0xx), 0.f);
        float a1 = fmaxf(fmaxf(b0ny - py, py - b0xy), 0.f);
        float a2 = fmaxf(fmaxf(b0nz - pz, pz - b0xz), 0.f);
        float m0 = a0 * a0 + a1 * a1 + a2 * a2;
        float c0f = fmaxf(fmaxf(b1nx - px, px - b1xx), 0.f);
        float c1f = fmaxf(fmaxf(b1ny - py, py - b1xy), 0.f);
        float c2f = fmaxf(fmaxf(b1nz - pz, pz - b1xz), 0.f);
        float m1 = c0f * c0f + c1f * c1f + c2f * c2f;
        bool fail0 = m0 < __uint_as_float((unsigned)(rk0 >> 32));
        bool fail1 = m1 < __uint_as_float((unsigned)(rk1 >> 32));
        if (!fail0 && !fail1) continue;

        const u64 nxp = pack2(-px, -px);
        const u64 nyp = pack2(-py, -py);
        const u64 nzp = pack2(-pz, -pz);

#pragma unroll
        for (int r = 0; r < 2; ++r) {
            if (r == 0 ? !fail0 : !fail1) continue;
            float bv = -1.0f; unsigned bc = 0;
#pragma unroll
            for (int j = 4 * r; j < 4 * r + 4; ++j) {
                float dx0, dx1, dy0, dy1, dz0, dz1;
                unpack2(add2(xp[j], nxp), dx0, dx1);
                unpack2(add2(yp[j], nyp), dy0, dy1);
                unpack2(add2(zp[j], nzp), dz0, dz1);
                float nd0 = dx0 * dx0 + dy0 * dy0 + dz0 * dz0;
                float nd1 = dx1 * dx1 + dy1 * dy1 + dz1 * dz1;
                float dk0 = fminf(d[2 * j],     nd0);
                float dk1 = fminf(d[2 * j + 1], nd1);
                d[2 * j]     = dk0;
                d[2 * j + 1] = dk1;
                if (dk0 > bv) { bv = dk0; bc = cpk[j] & 0xFFFFu; }
                if (dk1 > bv) { bv = dk1; bc = cpk[j] >> 16; }
            }
            unsigned ub = __float_as_uint(bv);
            unsigned m  = __reduce_max_sync(0xffffffffu, ub);
            unsigned cd = (ub == m) ? bc : 0u;
            unsigned cc = __reduce_max_sync(0xffffffffu, cd);
            if (r == 0) rk0 = ((u64)m << 32) | (u64)cc;
            else        rk1 = ((u64)m << 32) | (u64)cc;
        }
        wkey = rk0 > rk1 ? rk0 : rk1;
    }
}

// ---------------------------------------------------------------------------
// Gather + pointwise 2-layer MLP + output assembly.
// IDENT=true: downsample row index == output row index (nested-FPS theorem).
// ---------------------------------------------------------------------------
template <int CPREV, int F, bool REPEAT, bool IDENT>
__global__ __launch_bounds__(256)
void mlp_kernel(const float* __restrict__ in, const int* __restrict__ idx,
                const float* __restrict__ w1, const float* __restrict__ b1,
                const float* __restrict__ w2, const float* __restrict__ b2,
                float* __restrict__ out, int n_in, int npoints)
{
    constexpr int PPB = 256 / F;
    constexpr int CIN = REPEAT ? 2 * CPREV : CPREV;

    __shared__ float row[PPB][CPREV];
    __shared__ float hsm[PPB][F];

    const int t  = threadIdx.x;
    const int lp = t / F;
    const int g  = t % F;
    const int gp = blockIdx.x * PPB + lp;
    const int b  = gp / npoints;
    const int pt = gp % npoints;

    const int src = IDENT ? pt : idx[b * npoints + pt];
    const float* r = in + ((size_t)b * n_in + src) * CPREV;
    if (g < CPREV) row[lp][g] = r[g];
    __syncthreads();

    float acc = b1[g];
#pragma unroll
    for (int c = 0; c < CIN; ++c)
        acc += row[lp][c % CPREV] * w1[c * F + g];
    hsm[lp][g] = fmaxf(acc, 0.0f);
    __syncthreads();

    float o = b2[g];
#pragma unroll
    for (int j = 0; j < F; ++j)
        o += hsm[lp][j] * w2[j * F + g];

    float* orow = out + ((size_t)b * npoints + pt) * F;
    orow[g] = (g < 3) ? row[lp][g] : o;
}

// ---------------------------------------------------------------------------
// Launch
// ---------------------------------------------------------------------------
extern "C" void kernel_launch(void* const* d_in, const int* in_sizes, int n_in_cnt,
                              void* d_out, int out_size)
{
    (void)in_sizes; (void)n_in_cnt; (void)out_size;

    const float* pts  = (const float*)d_in[0];
    const float* w1_1 = (const float*)d_in[1];
    const float* b1_1 = (const float*)d_in[2];
    const float* w2_1 = (const float*)d_in[3];
    const float* b2_1 = (const float*)d_in[4];
    const float* w1_2 = (const float*)d_in[5];
    const float* b1_2 = (const float*)d_in[6];
    const float* w2_2 = (const float*)d_in[7];
    const float* b2_2 = (const float*)d_in[8];
    const float* w1_3 = (const float*)d_in[9];
    const float* b1_3 = (const float*)d_in[10];
    const float* w2_3 = (const float*)d_in[11];
    const float* b2_3 = (const float*)d_in[12];
    const float* w1_4 = (const float*)d_in[13];
    const float* b1_4 = (const float*)d_in[14];
    const float* w2_4 = (const float*)d_in[15];
    const float* b2_4 = (const float*)d_in[16];

    float* out = (float*)d_out;
    const int B = 8;
    float* f1 = out;                        // [8,4096,16]
    float* f2 = out + 8 * 4096 * 16;        // [8,2048,32]
    float* f3 = f2 + 8 * 2048 * 32;         // [8,1024,64]
    float* f4 = f3 + 8 * 1024 * 64;         // [8, 512,128]

    static int*    idx_buf = nullptr;
    static float4* sort_buf = nullptr;
    if (!idx_buf)  cudaGetSymbolAddress((void**)&idx_buf,  g_fps_idx);
    if (!sort_buf) cudaGetSymbolAddress((void**)&sort_buf, g_sorted);

    static bool attr_done = false;
    if (!attr_done) {
        cudaFuncSetAttribute(fps_kernel<8192>,
                             cudaFuncAttributeMaxDynamicSharedMemorySize, 8192 * 16);
        attr_done = true;
    }

    // Slot shims: launch indices 0-2, so ncu's fixed capture slot (index 3)
    // lands on the level-1 FPS kernel.
    probe_align_kernel<<<1, 32>>>();
    probe_align_kernel<<<1, 32>>>();
    probe_align_kernel<<<1, 32>>>();

    // ---- Level 1: 8192 -> 4096 — the ONLY FPS run ----
    fps_kernel<8192><<<B, 512, 8192 * 16>>>(pts, 3, 4096, idx_buf, sort_buf);
    mlp_kernel<3, 16, true, false><<<(B * 4096) / 16, 256>>>(
        pts, idx_buf, w1_1, b1_1, w2_1, b2_1, f1, 8192, 4096);

    // ---- Levels 2-4: nested-FPS theorem -> identity downsample ----
    mlp_kernel<16, 32, false, true><<<(B * 2048) / 8, 256>>>(
        f1, idx_buf, w1_2, b1_2, w2_2, b2_2, f2, 4096, 2048);

    mlp_kernel<32, 64, false, true><<<(B * 1024) / 4, 256>>>(
        f2, idx_buf, w1_3, b1_3, w2_3, b2_3, f3, 2048, 1024);

    mlp_kernel<64, 128, false, true><<<(B * 512) / 2, 256>>>(
        f3, idx_buf, w1_4, b1_4, w2_4, b2_4, f4, 1024, 512);
}